// round 15
// baseline (speedup 1.0000x reference)
#include <cuda_runtime.h>
#include <math.h>

#define NG   8
#define ND   16
#define NL   1024
#define NB   16
#define NE   8
#define NOUT 64
#define NKS  3
#define NK   4
#define NLP  1022
#define TILE 128
#define XPAD 136           // xs row stride (136%32=8 -> conflict-free B-frags)
#define HSP  72            // hs row stride for 64-col chunks (72%32=8)
#define WSP  65            // wef_s fold stride (overlaid on hs[0])

typedef unsigned int u32;

// Scratch (static device globals — no allocation)
__device__ float g_gates[NG*NB*NE];
__device__ volatile unsigned g_counter;   // zero-init; reset by loss block

__device__ __forceinline__ float tanh_fast(float x) {
    float r;
    asm("tanh.approx.f32 %0, %1;" : "=f"(r) : "f"(x));
    return r;
}
__device__ __forceinline__ float round_tf32(float x) {
    u32 r;
    asm("cvt.rna.tf32.f32 %0, %1;" : "=r"(r) : "f"(x));
    return __uint_as_float(r);
}
__device__ __forceinline__ u32 round_tf32_u(float x) {
    u32 r;
    asm("cvt.rna.tf32.f32 %0, %1;" : "=r"(r) : "f"(x));
    return r;
}
__device__ __forceinline__ void bar_grp(int id) {
    asm volatile("bar.sync %0, 128;" :: "r"(id) : "memory");
}
__device__ __forceinline__ void mma_tf32(float& c0, float& c1, float& c2, float& c3,
                                         u32 a0, u32 a1, u32 a2, u32 a3,
                                         u32 b0, u32 b1) {
    asm("mma.sync.aligned.m16n8k8.row.col.f32.tf32.tf32.f32 "
        "{%0,%1,%2,%3}, {%4,%5,%6,%7}, {%8,%9}, {%0,%1,%2,%3};"
        : "+f"(c0), "+f"(c1), "+f"(c2), "+f"(c3)
        : "r"(a0), "r"(a1), "r"(a2), "r"(a3), "r"(b0), "r"(b1));
}

__device__ __forceinline__ float cv_sq(const float* v) {
    float m = 0.f;
    #pragma unroll
    for (int i = 0; i < NE; i++) m += v[i];
    m *= (1.f / NE);
    float var = 0.f;
    #pragma unroll
    for (int i = 0; i < NE; i++) { float d = v[i] - m; var += d * d; }
    var *= (1.f / (NE - 1));
    return var / (m * m + 1e-10f);
}

// ---------------------------------------------------------------------------
// Fused kernel. grid (2, NB, NG) = 256 blocks, 256 threads = 2 groups x 128.
// Group gi handles tiles bx*4+gi*2+{0,1} with private xs/hs + named barriers.
// ---------------------------------------------------------------------------
__global__ __launch_bounds__(256, 3)
void fused_kernel(const float* __restrict__ x,
                  const float* __restrict__ w_gate,
                  const float* __restrict__ w1,
                  const float* __restrict__ b1,
                  const float* __restrict__ w2,
                  const float* __restrict__ b2,
                  float* __restrict__ out) {
    const int bx = blockIdx.x;    // 0..1
    const int b  = blockIdx.y;
    const int g  = blockIdx.z;
    const int blk = g * NB + b;

    __shared__ float  xs[2][ND * XPAD];   // per-group x tile
    __shared__ float  hs[2][NOUT * HSP];  // per-group h chunk (hs[0]: fold overlay)
    __shared__ float4 frag[1024];         // W_eff A-fragments (shared, RO after init)
    __shared__ float  b1s[NOUT];
    __shared__ float  bes[NOUT];
    __shared__ float  gsm[NE];

    const int t = threadIdx.x;
    const int c = t & 31;
    const int r = t >> 5;
    const int gi = r >> 2;         // group 0: warps 0-3; group 1: warps 4-7
    const int mt = r & 3;
    const int gid = c >> 2;
    const int tg  = c & 3;
    const int orow0 = mt * 16 + gid;

    const float* xb0 = x + (size_t)b * (NG * ND * NL) + (size_t)g * ND * NL;

    // ==== prologue step 1: warp 0 gates; warps 1-7 stage both groups' tile0 ====
    if (r == 0) {
        float plog[NE];
        #pragma unroll
        for (int e = 0; e < NE; e++) plog[e] = 0.f;
        #pragma unroll
        for (int i = c; i < ND * 5; i += 32) {
            int d = i / 5, j = i % 5;
            float xv = xb0[(size_t)d * NL + (NL - 6 + j)];
            const float4* w4 = (const float4*)(w_gate + ((size_t)g * ND * 5 + i) * NE);
            float4 wa = w4[0], wb = w4[1];
            plog[0] += xv * wa.x; plog[1] += xv * wa.y;
            plog[2] += xv * wa.z; plog[3] += xv * wa.w;
            plog[4] += xv * wb.x; plog[5] += xv * wb.y;
            plog[6] += xv * wb.z; plog[7] += xv * wb.w;
        }
        #pragma unroll
        for (int off = 16; off >= 1; off >>= 1)
            #pragma unroll
            for (int e = 0; e < NE; e++)
                plog[e] += __shfl_xor_sync(0xffffffffu, plog[e], off);

        float m = plog[0];
        #pragma unroll
        for (int e = 1; e < NE; e++) m = fmaxf(m, plog[e]);
        float p[NE]; float s = 0.f;
        #pragma unroll
        for (int e = 0; e < NE; e++) { p[e] = __expf(plog[e] - m); s += p[e]; }
        float inv = 1.f / s;
        #pragma unroll
        for (int e = 0; e < NE; e++) p[e] *= inv;

        int rank[NE];
        #pragma unroll
        for (int e = 0; e < NE; e++) {
            int rk = 0;
            #pragma unroll
            for (int j = 0; j < NE; j++)
                rk += (p[j] > p[e]) || (p[j] == p[e] && j < e);
            rank[e] = rk;
        }
        float s4 = 0.f;
        #pragma unroll
        for (int e = 0; e < NE; e++) s4 += (rank[e] < NK) ? p[e] : 0.f;
        const float invs4 = 1.f / (s4 + 1e-6f);

        if (c < NE) {
            const float gv = (rank[c] < NK) ? p[c] * invs4 : 0.f;
            gsm[c] = gv;
            if (bx == 0) {
                const size_t combine_sz = (size_t)NB * NG * NOUT * NLP;
                g_gates[blk * NE + c] = gv;
                out[combine_sz + 1 + (size_t)(b * NE + c) * NG + g] = gv;
            }
        }
        if (bx == 0 && c == 0) {
            __threadfence();
            atomicAdd((unsigned*)&g_counter, 1u);
        }
    } else {
        if (t - 32 < NOUT) b1s[t - 32] = b1[g * NOUT + (t - 32)];
        // stage 32 rows: buf 0 -> tile bx*4, buf 1 -> tile bx*4+2
        for (int dd = r - 1; dd < 2 * ND; dd += 7) {
            const int buf = dd >> 4, d = dd & 15;
            const int l0 = (bx * 4 + buf * 2) * TILE;
            const float* xrow = xb0 + (size_t)d * NL;
            float* srow = &xs[buf][d * XPAD];
            #pragma unroll
            for (int l = c; l < XPAD; l += 32) {
                const int gx = l0 + l;
                srow[l] = round_tf32((gx < NL) ? xrow[gx] : 0.f);
            }
        }
    }
    __syncthreads();

    // ==== prologue step 2: w1 A-fragments (regs) + W_eff fold into hs[0] ====
    u32 wf[6][4];
    {
        const float* w1g = w1 + (size_t)g * NOUT * (ND * NKS);
        #pragma unroll
        for (int ks = 0; ks < NKS; ks++)
            #pragma unroll
            for (int kt = 0; kt < 2; kt++) {
                const int colA = (kt * 8 + tg) * NKS + ks;
                const int colB = (kt * 8 + tg + 4) * NKS + ks;
                wf[ks * 2 + kt][0] = round_tf32_u(w1g[orow0 * 48 + colA]);
                wf[ks * 2 + kt][1] = round_tf32_u(w1g[(orow0 + 8) * 48 + colA]);
                wf[ks * 2 + kt][2] = round_tf32_u(w1g[orow0 * 48 + colB]);
                wf[ks * 2 + kt][3] = round_tf32_u(w1g[(orow0 + 8) * 48 + colB]);
            }
    }
    {
        float gv[NE];
        #pragma unroll
        for (int e = 0; e < NE; e++) gv[e] = gsm[e];
        const float* w2g = w2 + (size_t)g * NOUT * NE * NOUT;
        float* wef = hs[0];
        #pragma unroll
        for (int it = 0; it < (NOUT * NOUT) / 256; it++) {
            int idx = t + it * 256;
            int o = idx >> 6, k = idx & 63;
            const float* wrow = w2g + (size_t)o * NE * NOUT + k;
            float acc = 0.f;
            #pragma unroll
            for (int e = 0; e < NE; e++) acc += gv[e] * wrow[e * NOUT];
            wef[o * WSP + k] = round_tf32(acc);
        }
        if (t < NOUT) {
            const float* brow = b2 + (size_t)g * NOUT * NE + t * NE;
            float acc = 0.f;
            #pragma unroll
            for (int e = 0; e < NE; e++) acc += gv[e] * brow[e];
            bes[t] = acc;
        }
    }
    __syncthreads();

    // ==== prologue step 3: emit W_eff A-fragments ====
    {
        const float* wef = hs[0];
        #pragma unroll
        for (int it = 0; it < 4; it++) {
            int idx = t + it * 256;
            int lane = idx & 31, kt = (idx >> 5) & 7, fmt = idx >> 8;
            int fgid = lane >> 2, ftg = lane & 3;
            int k0 = kt * 8;
            float4 v;
            v.x = wef[(fmt * 16 + fgid)     * WSP + k0 + ftg];
            v.y = wef[(fmt * 16 + fgid + 8) * WSP + k0 + ftg];
            v.z = wef[(fmt * 16 + fgid)     * WSP + k0 + ftg + 4];
            v.w = wef[(fmt * 16 + fgid + 8) * WSP + k0 + ftg + 4];
            frag[idx] = v;
        }
    }
    __syncthreads();

    const float h_bv0 = b1s[orow0];
    const float h_bv1 = b1s[orow0 + 8];
    const float e_bv0 = bes[orow0];
    const float e_bv1 = bes[orow0 + 8];

    // ==== group pipelines (named barriers; groups never block each other) ====
    const int barid = gi + 1;
    const u32* xsu = (const u32*)xs[gi];
    const u32* hsu = (const u32*)hs[gi];
    float* hsf = hs[gi];

    #pragma unroll
    for (int it = 0; it < 2; it++) {
        const int tile = bx * 4 + gi * 2 + it;
        const int l0g  = tile * TILE;
        const int tlen = min(TILE, NLP - l0g);

        #pragma unroll
        for (int ch = 0; ch < 2; ch++) {
            // ---- phase 2: h-chunk = tanh(conv1) via tf32 mma (both halves) ----
            #pragma unroll
            for (int nh2 = 0; nh2 < 2; nh2++) {
                float cacc[4][4];
                #pragma unroll
                for (int nt = 0; nt < 4; nt++) {
                    cacc[nt][0] = h_bv0; cacc[nt][1] = h_bv0;
                    cacc[nt][2] = h_bv1; cacc[nt][3] = h_bv1;
                }
                #pragma unroll
                for (int ks = 0; ks < NKS; ks++)
                    #pragma unroll
                    for (int kt = 0; kt < 2; kt++) {
                        const u32 a0 = wf[ks * 2 + kt][0];
                        const u32 a1 = wf[ks * 2 + kt][1];
                        const u32 a2 = wf[ks * 2 + kt][2];
                        const u32 a3 = wf[ks * 2 + kt][3];
                        const int d0 = kt * 8;
                        #pragma unroll
                        for (int nt = 0; nt < 4; nt++) {
                            const int ncol = ch * 64 + nh2 * 32 + nt * 8 + gid + ks;
                            const u32 b0 = xsu[(d0 + tg) * XPAD + ncol];
                            const u32 b1v = xsu[(d0 + tg + 4) * XPAD + ncol];
                            mma_tf32(cacc[nt][0], cacc[nt][1], cacc[nt][2], cacc[nt][3],
                                     a0, a1, a2, a3, b0, b1v);
                        }
                    }
                #pragma unroll
                for (int nt = 0; nt < 4; nt++) {
                    const int colt = nh2 * 32 + nt * 8 + tg * 2;
                    *(float2*)&hsf[orow0 * HSP + colt] =
                        make_float2(round_tf32(tanh_fast(cacc[nt][0])),
                                    round_tf32(tanh_fast(cacc[nt][1])));
                    *(float2*)&hsf[(orow0 + 8) * HSP + colt] =
                        make_float2(round_tf32(tanh_fast(cacc[nt][2])),
                                    round_tf32(tanh_fast(cacc[nt][3])));
                }
            }
            bar_grp(barid);

            // restage this group's xs for its second tile (overlaps its phase 3)
            if (it == 0 && ch == 1) {
                const int l0g1 = (bx * 4 + gi * 2 + 1) * TILE;
                #pragma unroll
                for (int dq = 0; dq < 4; dq++) {
                    const int d = mt * 4 + dq;
                    const float* xrow = xb0 + (size_t)d * NL;
                    float* srow = &xs[gi][d * XPAD];
                    #pragma unroll
                    for (int l = c; l < XPAD; l += 32) {
                        const int gx = l0g1 + l;
                        srow[l] = round_tf32((gx < NL) ? xrow[gx] : 0.f);
                    }
                }
            }

            // ---- phase 3: out-chunk = W_eff @ h + b_eff (both halves) ----
            #pragma unroll
            for (int nh2 = 0; nh2 < 2; nh2++) {
                float cacc[4][4];
                #pragma unroll
                for (int nt = 0; nt < 4; nt++) {
                    cacc[nt][0] = e_bv0; cacc[nt][1] = e_bv0;
                    cacc[nt][2] = e_bv1; cacc[nt][3] = e_bv1;
                }
                #pragma unroll
                for (int kt = 0; kt < 8; kt++) {
                    const float4 af = frag[mt * 256 + kt * 32 + c];
                    const int k0 = kt * 8;
                    const u32 a0 = __float_as_uint(af.x);
                    const u32 a1 = __float_as_uint(af.y);
                    const u32 a2 = __float_as_uint(af.z);
                    const u32 a3 = __float_as_uint(af.w);
                    #pragma unroll
                    for (int nt = 0; nt < 4; nt++) {
                        const int ncol = nh2 * 32 + nt * 8 + gid;
                        const u32 b0 = hsu[(k0 + tg) * HSP + ncol];
                        const u32 b1v = hsu[(k0 + tg + 4) * HSP + ncol];
                        mma_tf32(cacc[nt][0], cacc[nt][1], cacc[nt][2], cacc[nt][3],
                                 a0, a1, a2, a3, b0, b1v);
                    }
                }
                #pragma unroll
                for (int nt = 0; nt < 4; nt++) {
                    const int colt = ch * 64 + nh2 * 32 + nt * 8 + tg * 2;
                    float* row0 = out + ((size_t)(b * NG + g) * NOUT + orow0) * NLP + l0g + colt;
                    float* row1 = out + ((size_t)(b * NG + g) * NOUT + orow0 + 8) * NLP + l0g + colt;
                    if (colt + 1 < tlen) {
                        *(float2*)row0 = make_float2(cacc[nt][0], cacc[nt][1]);
                        *(float2*)row1 = make_float2(cacc[nt][2], cacc[nt][3]);
                    } else if (colt < tlen) {
                        row0[0] = cacc[nt][0];
                        row1[0] = cacc[nt][2];
                    }
                }
            }
            bar_grp(barid);
        }
    }

    // ==== loss: block (0,0,0) waits for all 128 gate writers ====
    if (bx == 0 && b == 0 && g == 0) {
        if (t == 0) {
            while (g_counter < (unsigned)(NG * NB)) { }
            __threadfence();
        }
        __syncthreads();
        float* s_imp = (float*)xs;
        float* s_ld  = (float*)xs + NG * NE;
        float* lsum  = (float*)xs + 2 * NG * NE;
        if (t < NG * NE) {
            const int gg = t >> 3, e = t & 7;
            float imp = 0.f, ld = 0.f;
            #pragma unroll
            for (int bb = 0; bb < NB; bb++) {
                float v = g_gates[((gg * NB + bb) * NE) + e];
                imp += v;
                ld  += (v > 0.f) ? 1.f : 0.f;
            }
            s_imp[gg * NE + e] = imp;
            s_ld[gg * NE + e]  = ld;
        }
        __syncthreads();
        if (t < NG) lsum[t] = cv_sq(&s_imp[t * NE]) + cv_sq(&s_ld[t * NE]);
        __syncthreads();
        if (t == 0) {
            float total = 0.f;
            #pragma unroll
            for (int i = 0; i < NG; i++) total += lsum[i];
            out[(size_t)NB * NG * NOUT * NLP] = 0.01f * total;
            __threadfence();
            g_counter = 0u;   // reset for next graph replay
        }
    }
}

// ---------------------------------------------------------------------------
extern "C" void kernel_launch(void* const* d_in, const int* in_sizes, int n_in,
                              void* d_out, int out_size) {
    const float* x       = (const float*)d_in[0];
    const float* w_gate  = (const float*)d_in[1];
    const float* conv1_w = (const float*)d_in[2];
    const float* conv1_b = (const float*)d_in[3];
    const float* conv2_w = (const float*)d_in[4];
    const float* conv2_b = (const float*)d_in[5];
    float* out = (float*)d_out;

    fused_kernel<<<dim3(2, NB, NG), 256>>>(
        x, w_gate, conv1_w, conv1_b, conv2_w, conv2_b, out);
}

// round 16
// speedup vs baseline: 1.1219x; 1.1219x over previous
#include <cuda_runtime.h>
#include <math.h>

#define NG   8
#define ND   16
#define NL   1024
#define NB   16
#define NE   8
#define NOUT 64
#define NKS  3
#define NK   4
#define NLP  1022
#define TILE 128
#define NTILES 8
#define XPAD 136           // xs row stride: 136%32=8 -> conflict-free B-frags
#define HSP  136           // hs row stride

typedef unsigned int u32;

// Scratch (static device globals — no allocation)
__device__ float g_gates[NG*NB*NE];
__device__ float g_beff[NG*NB*NOUT];
// W_eff in mma-fragment order: [blk][mt(4)][kt(8)][lane(32)] x float4
__device__ float g_wfrag[NG*NB*4*8*32*4];
// conv1 weights in mma-fragment order: [g][mt(4)][ks(3)][kt(2)][lane(32)] x float4
__device__ float g_w1frag[NG*4*3*2*32*4];

__device__ __forceinline__ float tanh_fast(float x) {
    float r;
    asm("tanh.approx.f32 %0, %1;" : "=f"(r) : "f"(x));
    return r;
}
__device__ __forceinline__ float round_tf32(float x) {
    u32 r;
    asm("cvt.rna.tf32.f32 %0, %1;" : "=r"(r) : "f"(x));
    return __uint_as_float(r);
}
__device__ __forceinline__ void mma_tf32(float& c0, float& c1, float& c2, float& c3,
                                         u32 a0, u32 a1, u32 a2, u32 a3,
                                         u32 b0, u32 b1) {
    asm("mma.sync.aligned.m16n8k8.row.col.f32.tf32.tf32.f32 "
        "{%0,%1,%2,%3}, {%4,%5,%6,%7}, {%8,%9}, {%0,%1,%2,%3};"
        : "+f"(c0), "+f"(c1), "+f"(c2), "+f"(c3)
        : "r"(a0), "r"(a1), "r"(a2), "r"(a3), "r"(b0), "r"(b1));
}

__device__ __forceinline__ float cv_sq(const float* v) {
    float m = 0.f;
    #pragma unroll
    for (int i = 0; i < NE; i++) m += v[i];
    m *= (1.f / NE);
    float var = 0.f;
    #pragma unroll
    for (int i = 0; i < NE; i++) { float d = v[i] - m; var += d * d; }
    var *= (1.f / (NE - 1));
    return var / (m * m + 1e-10f);
}

// ---------------------------------------------------------------------------
// Kernel A: gates + W_eff fold -> fragment layout, 4x parallel over mt.
// grid (4, NB, NG): block (mt, b, g) folds W_eff rows [mt*16, mt*16+16).
// ---------------------------------------------------------------------------
__global__ __launch_bounds__(256)
void prep_kernel(const float* __restrict__ x,
                 const float* __restrict__ w_gate,
                 const float* __restrict__ w1,
                 const float* __restrict__ w2,
                 const float* __restrict__ b2,
                 float* __restrict__ out) {
    const int mt = blockIdx.x;    // 0..3
    const int b  = blockIdx.y;
    const int g  = blockIdx.z;
    const int blk = g * NB + b;
    const int t = threadIdx.x;
    const int c = t & 31;
    const int r = t >> 5;

    __shared__ float gsm[NE];
    __shared__ float wef_s[16 * 65];   // 16 rows x 64 cols, padded

    // ---- warp 0: gates (warp-parallel logits + rank top-k) ----
    if (r == 0) {
        const float* xb0 = x + (size_t)b * (NG * ND * NL) + (size_t)g * ND * NL;
        float plog[NE];
        #pragma unroll
        for (int e = 0; e < NE; e++) plog[e] = 0.f;
        #pragma unroll
        for (int i = c; i < ND * 5; i += 32) {
            int d = i / 5, j = i % 5;
            float xv = xb0[(size_t)d * NL + (NL - 6 + j)];
            const float4* w4 = (const float4*)(w_gate + ((size_t)g * ND * 5 + i) * NE);
            float4 wa = w4[0], wb = w4[1];
            plog[0] += xv * wa.x; plog[1] += xv * wa.y;
            plog[2] += xv * wa.z; plog[3] += xv * wa.w;
            plog[4] += xv * wb.x; plog[5] += xv * wb.y;
            plog[6] += xv * wb.z; plog[7] += xv * wb.w;
        }
        #pragma unroll
        for (int off = 16; off >= 1; off >>= 1)
            #pragma unroll
            for (int e = 0; e < NE; e++)
                plog[e] += __shfl_xor_sync(0xffffffffu, plog[e], off);

        float m = plog[0];
        #pragma unroll
        for (int e = 1; e < NE; e++) m = fmaxf(m, plog[e]);
        float p[NE]; float s = 0.f;
        #pragma unroll
        for (int e = 0; e < NE; e++) { p[e] = __expf(plog[e] - m); s += p[e]; }
        float inv = 1.f / s;
        #pragma unroll
        for (int e = 0; e < NE; e++) p[e] *= inv;

        int rank[NE];
        #pragma unroll
        for (int e = 0; e < NE; e++) {
            int rk = 0;
            #pragma unroll
            for (int j = 0; j < NE; j++)
                rk += (p[j] > p[e]) || (p[j] == p[e] && j < e);
            rank[e] = rk;
        }
        float s4 = 0.f;
        #pragma unroll
        for (int e = 0; e < NE; e++) s4 += (rank[e] < NK) ? p[e] : 0.f;
        const float invs4 = 1.f / (s4 + 1e-6f);

        if (c < NE) {
            const float gv = (rank[c] < NK) ? p[c] * invs4 : 0.f;
            gsm[c] = gv;
            if (mt == 0) {
                const size_t combine_sz = (size_t)NB * NG * NOUT * NLP;
                g_gates[blk * NE + c] = gv;
                out[combine_sz + 1 + (size_t)(b * NE + c) * NG + g] = gv;
            }
        }
    }

    // ---- (mt, b==0) blocks: conv1 weight fragments for (g, mt) ----
    if (b == 0 && t < 192) {
        const float* w1g = w1 + (size_t)g * NOUT * (ND * NKS);
        const int lane = t & 31;
        const int kt   = (t >> 5) & 1;
        const int ks   = t >> 6;          // 0..2
        const int fgid = lane >> 2, ftg = lane & 3;
        const int row0 = mt * 16 + fgid;
        const int colA = (kt * 8 + ftg) * NKS + ks;
        const int colB = (kt * 8 + ftg + 4) * NKS + ks;
        float4 v;
        v.x = round_tf32(w1g[row0 * (ND * NKS) + colA]);
        v.y = round_tf32(w1g[(row0 + 8) * (ND * NKS) + colA]);
        v.z = round_tf32(w1g[row0 * (ND * NKS) + colB]);
        v.w = round_tf32(w1g[(row0 + 8) * (ND * NKS) + colB]);
        ((float4*)g_w1frag)[(size_t)g * 768 + mt * 192 + ks * 64 + kt * 32 + lane] = v;
    }
    __syncthreads();

    // ---- fold this block's 16 W_eff rows: 1024 elements, 4 per thread ----
    {
        float gv[NE];
        #pragma unroll
        for (int e = 0; e < NE; e++) gv[e] = gsm[e];
        const float* w2g = w2 + (size_t)g * NOUT * NE * NOUT;
        #pragma unroll
        for (int it = 0; it < 4; it++) {
            int idx = t + it * 256;          // 0..1023
            int op = idx >> 6, k = idx & 63; // local row 0..15
            const float* wrow = w2g + (size_t)(mt * 16 + op) * NE * NOUT + k;
            float acc = 0.f;
            #pragma unroll
            for (int e = 0; e < NE; e++) acc += gv[e] * wrow[e * NOUT];
            wef_s[op * 65 + k] = round_tf32(acc);
        }
        if (mt == 0 && t < NOUT) {
            const float* brow = b2 + (size_t)g * NOUT * NE + t * NE;
            float acc = 0.f;
            #pragma unroll
            for (int e = 0; e < NE; e++) acc += gv[e] * brow[e];
            g_beff[blk * NOUT + t] = acc;
        }
    }
    __syncthreads();

    // ---- emit this mt's 256 fragment slots (coalesced float4 writes) ----
    {
        const int lane = t & 31, kt = t >> 5;   // t = kt*32 + lane, 256 slots
        const int fgid = lane >> 2, ftg = lane & 3;
        const int k0 = kt * 8;
        float4 v;
        v.x = wef_s[fgid * 65 + k0 + ftg];
        v.y = wef_s[(fgid + 8) * 65 + k0 + ftg];
        v.z = wef_s[fgid * 65 + k0 + ftg + 4];
        v.w = wef_s[(fgid + 8) * 65 + k0 + ftg + 4];
        ((float4*)g_wfrag)[(size_t)blk * 1024 + mt * 256 + t] = v;
    }
}

// ---------------------------------------------------------------------------
// Main kernel: conv1 + GEMM on the tensor pipe, 2 tiles per block.
// (Byte-identical to the R11 main that measured 28.0us.)
// grid (NTILES/2, NB, NG) = 512 blocks, 256 threads, 4 blocks/SM.
// ---------------------------------------------------------------------------
__global__ __launch_bounds__(256, 4)
void main_kernel(const float* __restrict__ x,
                 const float* __restrict__ b1,
                 float* __restrict__ out) {
    const int b   = blockIdx.y;
    const int g   = blockIdx.z;
    const int blk = g * NB + b;

    extern __shared__ float smem[];
    float* xs  = smem;                 // [d][l] 16*136 = 2176 (tf32)
    float* hs  = xs + ND * XPAD;       // [k][l] 64*136 = 8704 (tf32)
    float* b1s = hs + NOUT * HSP;      // 64

    const int t = threadIdx.x;
    const int c = t & 31;
    const int r = t >> 5;
    const int mt = r & 3;
    const int nh = r >> 2;
    const int gid = c >> 2;
    const int tg  = c & 3;
    const int orow0 = mt * 16 + gid;

    if (t < NOUT) b1s[t] = b1[g * NOUT + t];

    const float* xb0 = x + (size_t)b * (NG * ND * NL) + (size_t)g * ND * NL;
    const float4* wf1 = (const float4*)g_w1frag + (size_t)g * 768 + mt * 192 + c;
    const float4* wfr = (const float4*)g_wfrag + (size_t)blk * 1024 + mt * 256 + c;
    const float e_bv0 = g_beff[blk * NOUT + orow0];
    const float e_bv1 = g_beff[blk * NOUT + orow0 + 8];

    #pragma unroll
    for (int it = 0; it < 2; it++) {
        const int tile = blockIdx.x * 2 + it;
        const int l0g  = tile * TILE;
        const int tlen = min(TILE, NLP - l0g);

        // ---- stage x tile (tf32-rounded, zero-padded) ----
        for (int idx = t; idx < ND * XPAD; idx += 256) {
            const int d = idx / XPAD, l = idx % XPAD;
            const int gx = l0g + l;
            xs[idx] = round_tf32((gx < NL) ? xb0[(size_t)d * NL + gx] : 0.f);
        }
        __syncthreads();

        // ---- phase 2: h = tanh(conv1(x)) via tf32 mma (3 shifted GEMMs) ----
        {
            float cacc[8][4];
            const float bv0 = b1s[orow0];
            const float bv1 = b1s[orow0 + 8];
            #pragma unroll
            for (int nt = 0; nt < 8; nt++) {
                cacc[nt][0] = bv0; cacc[nt][1] = bv0;
                cacc[nt][2] = bv1; cacc[nt][3] = bv1;
            }
            const u32* xsu = (const u32*)xs;
            #pragma unroll
            for (int ks = 0; ks < NKS; ks++) {
                #pragma unroll
                for (int kt = 0; kt < 2; kt++) {
                    const float4 af = wf1[ks * 64 + kt * 32];
                    const u32 a0 = __float_as_uint(af.x);
                    const u32 a1 = __float_as_uint(af.y);
                    const u32 a2 = __float_as_uint(af.z);
                    const u32 a3 = __float_as_uint(af.w);
                    const int d0 = kt * 8;
                    #pragma unroll
                    for (int nt = 0; nt < 8; nt++) {
                        const int ncol = nh * 64 + nt * 8 + gid + ks;
                        const u32 b0 = xsu[(d0 + tg) * XPAD + ncol];
                        const u32 b1v = xsu[(d0 + tg + 4) * XPAD + ncol];
                        mma_tf32(cacc[nt][0], cacc[nt][1], cacc[nt][2], cacc[nt][3],
                                 a0, a1, a2, a3, b0, b1v);
                    }
                }
            }
            #pragma unroll
            for (int nt = 0; nt < 8; nt++) {
                const int colt = nh * 64 + nt * 8 + tg * 2;
                *(float2*)&hs[orow0 * HSP + colt] =
                    make_float2(round_tf32(tanh_fast(cacc[nt][0])),
                                round_tf32(tanh_fast(cacc[nt][1])));
                *(float2*)&hs[(orow0 + 8) * HSP + colt] =
                    make_float2(round_tf32(tanh_fast(cacc[nt][2])),
                                round_tf32(tanh_fast(cacc[nt][3])));
            }
        }
        __syncthreads();

        // ---- phase 3: out = W_eff @ h + b_eff via tf32 mma ----
        {
            float cacc[8][4];
            #pragma unroll
            for (int nt = 0; nt < 8; nt++) {
                cacc[nt][0] = e_bv0; cacc[nt][1] = e_bv0;
                cacc[nt][2] = e_bv1; cacc[nt][3] = e_bv1;
            }
            const u32* hsu = (const u32*)hs;
            #pragma unroll
            for (int kt = 0; kt < 8; kt++) {
                const float4 af = wfr[kt * 32];
                const int k0 = kt * 8;
                const u32 a0 = __float_as_uint(af.x);
                const u32 a1 = __float_as_uint(af.y);
                const u32 a2 = __float_as_uint(af.z);
                const u32 a3 = __float_as_uint(af.w);
                #pragma unroll
                for (int nt = 0; nt < 8; nt++) {
                    const int ncol = nh * 64 + nt * 8 + gid;
                    const u32 b0 = hsu[(k0 + tg) * HSP + ncol];
                    const u32 b1v = hsu[(k0 + tg + 4) * HSP + ncol];
                    mma_tf32(cacc[nt][0], cacc[nt][1], cacc[nt][2], cacc[nt][3],
                             a0, a1, a2, a3, b0, b1v);
                }
            }
            #pragma unroll
            for (int nt = 0; nt < 8; nt++) {
                const int colt = nh * 64 + nt * 8 + tg * 2;
                float* row0 = out + ((size_t)(b * NG + g) * NOUT + orow0) * NLP + l0g + colt;
                float* row1 = out + ((size_t)(b * NG + g) * NOUT + orow0 + 8) * NLP + l0g + colt;
                if (colt + 1 < tlen) {
                    *(float2*)row0 = make_float2(cacc[nt][0], cacc[nt][1]);
                    *(float2*)row1 = make_float2(cacc[nt][2], cacc[nt][3]);
                } else if (colt < tlen) {
                    row0[0] = cacc[nt][0];
                    row1[0] = cacc[nt][2];
                }
            }
        }
        __syncthreads();
    }

    // ---- loss tail: block (0,0,0) only; g_gates written by prep_kernel ----
    if (blockIdx.x == 0 && b == 0 && g == 0) {
        float* s_imp = smem;
        float* s_ld  = smem + NG * NE;
        float* lsum  = smem + 2 * NG * NE;
        if (t < NG * NE) {
            const int gg = t >> 3, e = t & 7;
            float imp = 0.f, ld = 0.f;
            #pragma unroll
            for (int bb = 0; bb < NB; bb++) {
                float v = g_gates[((gg * NB + bb) * NE) + e];
                imp += v;
                ld  += (v > 0.f) ? 1.f : 0.f;
            }
            s_imp[gg * NE + e] = imp;
            s_ld[gg * NE + e]  = ld;
        }
        __syncthreads();
        if (t < NG) lsum[t] = cv_sq(&s_imp[t * NE]) + cv_sq(&s_ld[t * NE]);
        __syncthreads();
        if (t == 0) {
            float total = 0.f;
            #pragma unroll
            for (int i = 0; i < NG; i++) total += lsum[i];
            out[(size_t)NB * NG * NOUT * NLP] = 0.01f * total;
        }
    }
}

// ---------------------------------------------------------------------------
extern "C" void kernel_launch(void* const* d_in, const int* in_sizes, int n_in,
                              void* d_out, int out_size) {
    const float* x       = (const float*)d_in[0];
    const float* w_gate  = (const float*)d_in[1];
    const float* conv1_w = (const float*)d_in[2];
    const float* conv1_b = (const float*)d_in[3];
    const float* conv2_w = (const float*)d_in[4];
    const float* conv2_b = (const float*)d_in[5];
    float* out = (float*)d_out;

    const int smem_bytes = (ND * XPAD + NOUT * HSP + NOUT) * sizeof(float);
    cudaFuncSetAttribute(main_kernel,
                         cudaFuncAttributeMaxDynamicSharedMemorySize, smem_bytes);

    prep_kernel<<<dim3(4, NB, NG), 256>>>(x, w_gate, conv1_w, conv2_w, conv2_b, out);
    main_kernel<<<dim3(NTILES / 2, NB, NG), 256, smem_bytes>>>(x, conv1_b, out);
}